// round 2
// baseline (speedup 1.0000x reference)
#include <cuda_runtime.h>
#include <cuda_bf16.h>

#define NN 100000
#define NE 800000
#define DD 300
#define DP 320          // padded row stride (floats) -> 160 float2 lanes
#define NG 64

// ---------------- scratch (device globals; no allocation allowed) ----------
__device__ int   g_cnt[NN];
__device__ int   g_rowptr[NN + 1];
__device__ int   g_wpos[NN];
__device__ int   g_col[NE];
__device__ float g_dinv[NN];
__device__ float g_bufA[(size_t)NN * DP];
__device__ float g_bufB[(size_t)NN * DP];
__device__ float g_v1[NN];
__device__ float g_v2[NN];
__device__ float g_Msum[NG * DD];
__device__ float g_usum[2 * NG];   // [0..63]=sum v1 per graph, [64..127]=sum v2
__device__ int   g_gcnt[NG];
__device__ float g_W2[DD * DD];
__device__ float g_W3[DD * DD];
__device__ float g_r1[DD];
__device__ float g_r2[DD];

// ---------------- kernels ---------------------------------------------------

__global__ void zero_kernel() {
    int idx = blockIdx.x * blockDim.x + threadIdx.x;
    int stride = gridDim.x * blockDim.x;
    for (int i = idx; i < NN; i += stride) g_cnt[i] = 0;
    for (int i = idx; i < NG * DD; i += stride) g_Msum[i] = 0.f;
    for (int i = idx; i < 2 * NG; i += stride) g_usum[i] = 0.f;
    for (int i = idx; i < NG; i += stride) g_gcnt[i] = 0;
}

__global__ void hist_kernel(const int* __restrict__ ei) {
    int e = blockIdx.x * blockDim.x + threadIdx.x;
    if (e >= NE) return;
    atomicAdd(&g_cnt[ei[NE + e]], 1);   // dst
}

// single-block exclusive scan over g_cnt -> g_rowptr, also dinv
__global__ void scan_kernel() {
    __shared__ int sh[1024];
    int tid = threadIdx.x;
    const int per = (NN + 1023) / 1024;
    int start = tid * per;
    int end = start + per; if (end > NN) end = NN; if (start > NN) start = NN;
    int s = 0;
    for (int i = start; i < end; ++i) s += g_cnt[i];
    sh[tid] = s;
    __syncthreads();
    for (int off = 1; off < 1024; off <<= 1) {
        int v = 0;
        if (tid >= off) v = sh[tid - off];
        __syncthreads();
        sh[tid] += v;
        __syncthreads();
    }
    int run = (tid > 0) ? sh[tid - 1] : 0;
    for (int i = start; i < end; ++i) {
        g_rowptr[i] = run;
        g_wpos[i]   = run;
        g_dinv[i]   = rsqrtf((float)(g_cnt[i] + 1));   // +1 self loop
        run += g_cnt[i];
    }
    if (tid == 1023) g_rowptr[NN] = sh[1023];
}

__global__ void scatter_kernel(const int* __restrict__ ei) {
    int e = blockIdx.x * blockDim.x + threadIdx.x;
    if (e >= NE) return;
    int dst = ei[NE + e];
    int pos = atomicAdd(&g_wpos[dst], 1);
    g_col[pos] = ei[e];                 // src
}

// h0[i] = atom_table[x[i,0]] + word_table[x[i,1]], written padded to DP
__global__ void embed_kernel(const int* __restrict__ x,
                             const float* __restrict__ at,
                             const float* __restrict__ wt) {
    int i = blockIdx.x;
    int t = threadIdx.x;                // 0..159
    int a = x[2 * i];
    int w = x[2 * i + 1];
    float2 v = make_float2(0.f, 0.f);
    if (t < DD / 2) {
        const float2* a2 = (const float2*)at;
        const float2* w2 = (const float2*)wt;
        float2 va = a2[a * (DD / 2) + t];
        float2 vw = w2[w * (DD / 2) + t];
        v.x = va.x + vw.x;
        v.y = va.y + vw.y;
    }
    ((float2*)g_bufA)[(size_t)i * (DP / 2) + t] = v;
}

// y[i] = dinv[i] * ( sum_{e: dst=i} dinv[src]*x[src] + dinv[i]*x[i] )
__global__ void agg_kernel(const float* __restrict__ xin, float* __restrict__ yout) {
    int i = blockIdx.x;
    int t = threadIdx.x;                // 0..159 -> float2 lane
    int beg = g_rowptr[i];
    int end = g_rowptr[i + 1];
    const float2* x2 = (const float2*)xin;
    float2 acc = make_float2(0.f, 0.f);
    for (int e = beg; e < end; ++e) {
        int s = g_col[e];
        float w = g_dinv[s];
        float2 v = __ldg(&x2[(size_t)s * (DP / 2) + t]);
        acc.x += w * v.x;
        acc.y += w * v.y;
    }
    float di = g_dinv[i];
    float2 vs = x2[(size_t)i * (DP / 2) + t];
    acc.x = di * (acc.x + di * vs.x);
    acc.y = di * (acc.y + di * vs.y);
    ((float2*)yout)[(size_t)i * (DP / 2) + t] = acc;
}

// scalar aggregation; ones=1 means input vector is all-ones
__global__ void aggs_kernel(const float* __restrict__ vin, float* __restrict__ vout, int ones) {
    int i = blockIdx.x * blockDim.x + threadIdx.x;
    if (i >= NN) return;
    int beg = g_rowptr[i];
    int end = g_rowptr[i + 1];
    float sum = 0.f;
    for (int e = beg; e < end; ++e) {
        int s = g_col[e];
        float w = g_dinv[s];
        sum += ones ? w : w * vin[s];
    }
    float di = g_dinv[i];
    float self = ones ? 1.f : vin[i];
    vout[i] = di * (sum + di * self);
}

// mean-pool partial sums (batch is sorted): run-length accumulate then atomic flush
__global__ void pool_kernel(const float* __restrict__ h, const int* __restrict__ batch) {
    const int CH = 512;
    int n0 = blockIdx.x * CH;
    int n1 = n0 + CH; if (n1 > NN) n1 = NN;
    int t = threadIdx.x;                // 0..319, only t<300 carries data
    float acc = 0.f;
    int cur = batch[n0];
    for (int n = n0; n < n1; ++n) {
        int g = batch[n];
        if (g != cur) {
            if (t < DD) atomicAdd(&g_Msum[cur * DD + t], acc);
            acc = 0.f;
            cur = g;
        }
        if (t < DD) acc += h[(size_t)n * DP + t];
    }
    if (t < DD) atomicAdd(&g_Msum[cur * DD + t], acc);
}

__global__ void vpool_kernel(const int* __restrict__ batch) {
    int i = blockIdx.x * blockDim.x + threadIdx.x;
    if (i >= NN) return;
    int bg = batch[i];
    atomicAdd(&g_gcnt[bg], 1);
    atomicAdd(&g_usum[bg], g_v1[i]);
    atomicAdd(&g_usum[NG + bg], g_v2[i]);
}

// C = A @ B, all 300x300 row-major
__global__ void gemm300_kernel(const float* __restrict__ A,
                               const float* __restrict__ B,
                               float* __restrict__ C) {
    int r = blockIdx.x;
    int c = threadIdx.x;
    if (c >= DD) return;
    float acc = 0.f;
    for (int k = 0; k < DD; ++k) acc += A[r * DD + k] * B[k * DD + c];
    C[r * DD + c] = acc;
}

// r1 = b^T W, r2 = b^T W2
__global__ void rvec_kernel(const float* __restrict__ b,
                            const float* __restrict__ W) {
    int c = blockIdx.x * blockDim.x + threadIdx.x;
    if (c >= DD) return;
    float a1 = 0.f, a2 = 0.f;
    for (int k = 0; k < DD; ++k) {
        float bk = b[k];
        a1 += bk * W[k * DD + c];
        a2 += bk * g_W2[k * DD + c];
    }
    g_r1[c] = a1;
    g_r2[c] = a2;
}

// out[g] = (Msum[g]@W3 + u2sum*r2 + u1sum*r1)/max(cnt,1) + (cnt>0)*b
__global__ void final_kernel(const float* __restrict__ bvec, float* __restrict__ out) {
    int g = blockIdx.x;
    int d = threadIdx.x;
    if (d >= DD) return;
    float acc = 0.f;
    for (int k = 0; k < DD; ++k) acc += g_Msum[g * DD + k] * g_W3[k * DD + d];
    int c = g_gcnt[g];
    float denom = (c > 0) ? (float)c : 1.f;
    float res = (acc + g_usum[NG + g] * g_r2[d] + g_usum[g] * g_r1[d]) / denom;
    if (c > 0) res += bvec[d];
    out[g * DD + d] = res;
}

// ---------------- launch ----------------------------------------------------

extern "C" void kernel_launch(void* const* d_in, const int* in_sizes, int n_in,
                              void* d_out, int out_size) {
    const int*   x     = (const int*)d_in[0];     // [N,2]
    const int*   ei    = (const int*)d_in[1];     // [2,E]
    const int*   batch = (const int*)d_in[2];     // [N]
    const float* at    = (const float*)d_in[3];   // [41,300]
    const float* wt    = (const float*)d_in[4];   // [10000,300]
    const float* W     = (const float*)d_in[5];   // [300,300]
    const float* b     = (const float*)d_in[6];   // [300]
    float* out = (float*)d_out;

    float *bufA, *bufB, *v1, *v2, *W2p, *W3p;
    cudaGetSymbolAddress((void**)&bufA, g_bufA);
    cudaGetSymbolAddress((void**)&bufB, g_bufB);
    cudaGetSymbolAddress((void**)&v1,   g_v1);
    cudaGetSymbolAddress((void**)&v2,   g_v2);
    cudaGetSymbolAddress((void**)&W2p,  g_W2);
    cudaGetSymbolAddress((void**)&W3p,  g_W3);

    // 1) zero accumulators
    zero_kernel<<<512, 256>>>();
    // 2) CSR build (by dst)
    hist_kernel<<<(NE + 255) / 256, 256>>>(ei);
    scan_kernel<<<1, 1024>>>();
    scatter_kernel<<<(NE + 255) / 256, 256>>>(ei);
    // 3) embedding -> bufA
    embed_kernel<<<NN, 160>>>(x, at, wt);
    // 4) three hops of aggregation (no per-hop GEMM; W^3 applied at the end)
    agg_kernel<<<NN, 160>>>(bufA, bufB);
    agg_kernel<<<NN, 160>>>(bufB, bufA);
    agg_kernel<<<NN, 160>>>(bufA, bufB);   // result in bufB
    // 5) scalar aggregations for the bias terms: v1 = A*1, v2 = A*v1
    aggs_kernel<<<(NN + 255) / 256, 256>>>(nullptr, v1, 1);
    aggs_kernel<<<(NN + 255) / 256, 256>>>(v1, v2, 0);
    // 6) pooling partial sums
    pool_kernel<<<(NN + 511) / 512, 320>>>(bufB, batch);
    vpool_kernel<<<(NN + 255) / 256, 256>>>(batch);
    // 7) tiny GEMMs: W2 = W@W, W3 = W2@W, r-vectors
    gemm300_kernel<<<DD, 320>>>(W, W, W2p);
    gemm300_kernel<<<DD, 320>>>(W2p, W, W3p);
    rvec_kernel<<<1, 320>>>(b, W);
    // 8) finisher: 64x300 output
    final_kernel<<<NG, 320>>>(b, out);
}